// round 6
// baseline (speedup 1.0000x reference)
#include <cuda_runtime.h>
#include <cuda_bf16.h>
#include <cuda_fp8.h>
#include <math.h>
#include <stdint.h>

// Problem shape (FineGrainedFP8SwiGLUMLP): x[M,H], gate/up [I,H], down [H,I]
#define M_DIM 4096
#define H_DIM 4096
#define I_DIM 14336
#define KB_H (H_DIM / 128)   // 32
#define KB_I (I_DIM / 128)   // 112

// ---------------- scratch (device globals; no allocation) ----------------
__device__ __nv_bfloat16 g_Aq[(size_t)M_DIM * H_DIM];          // quantized x codes (exact e4m3 in bf16)
__device__ float         g_Ascale[(size_t)M_DIM * KB_H];
__device__ __nv_bfloat16 g_Wg[(size_t)I_DIM * H_DIM];
__device__ __nv_bfloat16 g_Wu[(size_t)I_DIM * H_DIM];
__device__ __nv_bfloat16 g_Wd[(size_t)H_DIM * I_DIM];
__device__ float         g_gate[(size_t)M_DIM * I_DIM];
__device__ float         g_up[(size_t)M_DIM * I_DIM];
__device__ __nv_bfloat16 g_Hq[(size_t)M_DIM * I_DIM];
__device__ float         g_Hscale[(size_t)M_DIM * KB_I];
__device__ int           g_wfmt;   // 0 = raw e4m3 bytes, 1 = float32, 2 = bfloat16

// ---------------- weight dtype detection (device-side, deterministic) ----------------
__global__ void detect_kernel(const void* __restrict__ w) {
    __shared__ int c32, c16;
    int t = threadIdx.x;
    if (t == 0) { c32 = 0; c16 = 0; }
    __syncthreads();
    const float* f = (const float*)w;
    const __nv_bfloat16* b = (const __nv_bfloat16*)w;
    int l32 = 0, l16 = 0;
    for (int i = t; i < 16384; i += 256) {
        float v = f[i];
        if (fabsf(v) <= 448.0f) l32++;          // NaN/Inf fail this compare
        float u = __bfloat162float(b[i]);
        if (fabsf(u) <= 448.0f) l16++;
    }
    atomicAdd(&c32, l32);
    atomicAdd(&c16, l16);
    __syncthreads();
    if (t == 0) {
        int fmt = 0;
        if (c32 >= 16056) fmt = 1;              // 98% of 16384
        else if (c16 >= 16056) fmt = 2;
        g_wfmt = fmt;
    }
}

// ---------------- weight convert -> bf16 quantized codes ----------------
__global__ void convert_w_kernel(const void* __restrict__ src,
                                 __nv_bfloat16* __restrict__ dst, size_t n) {
    int fmt = g_wfmt;
    size_t i = (size_t)blockIdx.x * blockDim.x + threadIdx.x;
    size_t stride = (size_t)gridDim.x * blockDim.x;
    if (fmt == 1) {
        const float* s = (const float*)src;
        for (; i < n; i += stride) dst[i] = __float2bfloat16(s[i]);   // e4m3 values -> exact
    } else if (fmt == 2) {
        const __nv_bfloat16* s = (const __nv_bfloat16*)src;
        for (; i < n; i += stride) dst[i] = s[i];
    } else {
        const __nv_fp8_e4m3* s = (const __nv_fp8_e4m3*)src;
        for (; i < n; i += stride) dst[i] = __float2bfloat16((float)s[i]);
    }
}

// ---------------- per-token per-128-group fake-quant of activations ----------------
// One block of 128 threads per (row, group). Stores e4m3 codes (bf16) + fp32 scale.
__global__ void quant_act_kernel(const float* __restrict__ X,
                                 __nv_bfloat16* __restrict__ Q,
                                 float* __restrict__ S, int Kdim) {
    const int KB = Kdim >> 7;
    const int g = blockIdx.x;
    const int m = blockIdx.y;
    const int t = threadIdx.x;
    size_t base = (size_t)m * Kdim + (size_t)g * 128;
    float v = X[base + t];
    float a = fabsf(v);
#pragma unroll
    for (int o = 16; o > 0; o >>= 1) a = fmaxf(a, __shfl_xor_sync(0xffffffffu, a, o));
    __shared__ float red[4];
    if ((t & 31) == 0) red[t >> 5] = a;
    __syncthreads();
    float amax = fmaxf(fmaxf(red[0], red[1]), fmaxf(red[2], red[3]));
    float s = fmaxf(amax * (1.0f / 448.0f), 1e-12f);
    float qv = v / s;
    qv = fminf(fmaxf(qv, -448.0f), 448.0f);
    __nv_fp8_e4m3 f8(qv);                  // cvt.rn.satfinite == jax RNE
    Q[base + t] = __float2bfloat16((float)f8);
    if (t == 0) S[(size_t)m * KB + g] = s;
}

// ---------------- silu(gate)*up + fake-quant ----------------
__global__ void silu_quant_kernel(const float* __restrict__ G,
                                  const float* __restrict__ U,
                                  __nv_bfloat16* __restrict__ Q,
                                  float* __restrict__ S, int Kdim) {
    const int KB = Kdim >> 7;
    const int g = blockIdx.x;
    const int m = blockIdx.y;
    const int t = threadIdx.x;
    size_t base = (size_t)m * Kdim + (size_t)g * 128;
    float gv = G[base + t];
    float uv = U[base + t];
    float v = (gv / (1.0f + expf(-gv))) * uv;
    float a = fabsf(v);
#pragma unroll
    for (int o = 16; o > 0; o >>= 1) a = fmaxf(a, __shfl_xor_sync(0xffffffffu, a, o));
    __shared__ float red[4];
    if ((t & 31) == 0) red[t >> 5] = a;
    __syncthreads();
    float amax = fmaxf(fmaxf(red[0], red[1]), fmaxf(red[2], red[3]));
    float s = fmaxf(amax * (1.0f / 448.0f), 1e-12f);
    float qv = v / s;
    qv = fminf(fmaxf(qv, -448.0f), 448.0f);
    __nv_fp8_e4m3 f8(qv);
    Q[base + t] = __float2bfloat16((float)f8);
    if (t == 0) S[(size_t)m * KB + g] = s;
}

// ---------------- block-scaled GEMM: C[m,n] = sum_kb as[m,kb]*ws[nb,kb]*(Aq . Wq) ----------------
#define BM 128
#define BN 128
#define BK 64
#define BKP 72   // +8 bf16 pad -> 144B row stride -> conflict-free ldmatrix

__device__ __forceinline__ void mma16816(float* c, const uint32_t* a, const uint32_t* b) {
    asm volatile(
        "mma.sync.aligned.m16n8k16.row.col.f32.bf16.bf16.f32 "
        "{%0,%1,%2,%3},{%4,%5,%6,%7},{%8,%9},{%0,%1,%2,%3};\n"
        : "+f"(c[0]), "+f"(c[1]), "+f"(c[2]), "+f"(c[3])
        : "r"(a[0]), "r"(a[1]), "r"(a[2]), "r"(a[3]), "r"(b[0]), "r"(b[1]));
}
__device__ __forceinline__ void ldsm4(uint32_t* r, uint32_t addr) {
    asm volatile("ldmatrix.sync.aligned.m8n8.x4.shared.b16 {%0,%1,%2,%3},[%4];\n"
                 : "=r"(r[0]), "=r"(r[1]), "=r"(r[2]), "=r"(r[3]) : "r"(addr));
}
__device__ __forceinline__ void ldsm2(uint32_t* r, uint32_t addr) {
    asm volatile("ldmatrix.sync.aligned.m8n8.x2.shared.b16 {%0,%1},[%2];\n"
                 : "=r"(r[0]), "=r"(r[1]) : "r"(addr));
}
__device__ __forceinline__ uint32_t s2u(const void* p) {
    return (uint32_t)__cvta_generic_to_shared(p);
}

__global__ void __launch_bounds__(256, 1)
gemm_q(const __nv_bfloat16* __restrict__ A, const float* __restrict__ As,
       const __nv_bfloat16* __restrict__ B, const float* __restrict__ Bs,
       float* __restrict__ C, int Ndim, int Kdim) {
    __shared__ __nv_bfloat16 sA[BM][BKP];
    __shared__ __nv_bfloat16 sB[BN][BKP];

    const int KB = Kdim >> 7;
    const int tid = threadIdx.x;
    const int lane = tid & 31;
    const int w = tid >> 5;
    const int wm = (w & 3) * 32;   // warp m offset within CTA
    const int wn = (w >> 2) * 64;  // warp n offset within CTA
    const int m0 = blockIdx.y * BM;
    const int n0 = blockIdx.x * BN;
    const int nb = n0 >> 7;        // weight-scale n block

    // ldmatrix per-lane smem row/col offsets
    const int a_r = (((lane >> 3) & 1) << 3) + (lane & 7);   // row within 16
    const int a_k = (lane >> 4) << 3;                        // 0 or 8
    const int b_r = lane & 7;
    const int b_k = ((lane >> 3) & 1) << 3;

    float fc[2][8][4], pc[2][8][4];
#pragma unroll
    for (int i = 0; i < 2; i++)
#pragma unroll
        for (int j = 0; j < 8; j++)
#pragma unroll
            for (int k = 0; k < 4; k++) { fc[i][j][k] = 0.0f; pc[i][j][k] = 0.0f; }

    for (int kb = 0; kb < KB; kb++) {
#pragma unroll
        for (int h = 0; h < 2; h++) {
            const int k0 = kb * 128 + h * BK;
            __syncthreads();   // previous tile fully consumed
#pragma unroll
            for (int i = 0; i < 4; i++) {
                int idx = i * 256 + tid;
                int r = idx >> 3, ch = idx & 7;
                *(uint4*)(&sA[r][ch * 8]) =
                    *(const uint4*)(A + (size_t)(m0 + r) * Kdim + k0 + ch * 8);
                *(uint4*)(&sB[r][ch * 8]) =
                    *(const uint4*)(B + (size_t)(n0 + r) * Kdim + k0 + ch * 8);
            }
            __syncthreads();
#pragma unroll
            for (int ks = 0; ks < 4; ks++) {
                uint32_t af[2][4], bf[8][2];
#pragma unroll
                for (int mt = 0; mt < 2; mt++)
                    ldsm4(af[mt], s2u(&sA[wm + mt * 16 + a_r][ks * 16 + a_k]));
#pragma unroll
                for (int nt = 0; nt < 8; nt++)
                    ldsm2(bf[nt], s2u(&sB[wn + nt * 8 + b_r][ks * 16 + b_k]));
#pragma unroll
                for (int mt = 0; mt < 2; mt++)
#pragma unroll
                    for (int nt = 0; nt < 8; nt++)
                        mma16816(pc[mt][nt], af[mt], bf[nt]);
            }
        }
        // promote: final += ascale*wscale * partial (per 128-K block)
        float ws = Bs[(size_t)nb * KB + kb];
#pragma unroll
        for (int mt = 0; mt < 2; mt++) {
            int r0 = m0 + wm + mt * 16 + (lane >> 2);
            float s0 = As[(size_t)r0 * KB + kb] * ws;
            float s1 = As[(size_t)(r0 + 8) * KB + kb] * ws;
#pragma unroll
            for (int nt = 0; nt < 8; nt++) {
                fc[mt][nt][0] += s0 * pc[mt][nt][0];
                fc[mt][nt][1] += s0 * pc[mt][nt][1];
                fc[mt][nt][2] += s1 * pc[mt][nt][2];
                fc[mt][nt][3] += s1 * pc[mt][nt][3];
                pc[mt][nt][0] = 0.0f; pc[mt][nt][1] = 0.0f;
                pc[mt][nt][2] = 0.0f; pc[mt][nt][3] = 0.0f;
            }
        }
    }
    // epilogue
#pragma unroll
    for (int mt = 0; mt < 2; mt++) {
        int r0 = m0 + wm + mt * 16 + (lane >> 2);
#pragma unroll
        for (int nt = 0; nt < 8; nt++) {
            int c0 = n0 + wn + nt * 8 + (lane & 3) * 2;
            *(float2*)(C + (size_t)r0 * Ndim + c0) =
                make_float2(fc[mt][nt][0], fc[mt][nt][1]);
            *(float2*)(C + (size_t)(r0 + 8) * Ndim + c0) =
                make_float2(fc[mt][nt][2], fc[mt][nt][3]);
        }
    }
}

// ---------------- launch ----------------
extern "C" void kernel_launch(void* const* d_in, const int* in_sizes, int n_in,
                              void* d_out, int out_size) {
    (void)in_sizes; (void)n_in; (void)out_size;
    const float* x  = (const float*)d_in[0];
    const void*  gw = d_in[1];
    const float* gs = (const float*)d_in[2];
    const void*  uw = d_in[3];
    const float* us = (const float*)d_in[4];
    const void*  dw = d_in[5];
    const float* ds = (const float*)d_in[6];
    float* out = (float*)d_out;

    static bool init = false;
    static void *pAq, *pAs, *pWg, *pWu, *pWd, *pG, *pU, *pHq, *pHs;
    if (!init) {
        cudaGetSymbolAddress(&pAq, g_Aq);
        cudaGetSymbolAddress(&pAs, g_Ascale);
        cudaGetSymbolAddress(&pWg, g_Wg);
        cudaGetSymbolAddress(&pWu, g_Wu);
        cudaGetSymbolAddress(&pWd, g_Wd);
        cudaGetSymbolAddress(&pG,  g_gate);
        cudaGetSymbolAddress(&pU,  g_up);
        cudaGetSymbolAddress(&pHq, g_Hq);
        cudaGetSymbolAddress(&pHs, g_Hscale);
        init = true;
    }

    detect_kernel<<<1, 256>>>(gw);
    convert_w_kernel<<<4096, 256>>>(gw, (__nv_bfloat16*)pWg, (size_t)I_DIM * H_DIM);
    convert_w_kernel<<<4096, 256>>>(uw, (__nv_bfloat16*)pWu, (size_t)I_DIM * H_DIM);
    convert_w_kernel<<<4096, 256>>>(dw, (__nv_bfloat16*)pWd, (size_t)H_DIM * I_DIM);

    quant_act_kernel<<<dim3(KB_H, M_DIM), 128>>>(x, (__nv_bfloat16*)pAq, (float*)pAs, H_DIM);

    dim3 grid1(I_DIM / BN, M_DIM / BM);
    gemm_q<<<grid1, 256>>>((__nv_bfloat16*)pAq, (float*)pAs,
                           (__nv_bfloat16*)pWg, gs, (float*)pG, I_DIM, H_DIM);
    gemm_q<<<grid1, 256>>>((__nv_bfloat16*)pAq, (float*)pAs,
                           (__nv_bfloat16*)pWu, us, (float*)pU, I_DIM, H_DIM);

    silu_quant_kernel<<<dim3(KB_I, M_DIM), 128>>>((float*)pG, (float*)pU,
                                                  (__nv_bfloat16*)pHq, (float*)pHs, I_DIM);

    dim3 grid2(H_DIM / BN, M_DIM / BM);
    gemm_q<<<grid2, 256>>>((__nv_bfloat16*)pHq, (float*)pHs,
                           (__nv_bfloat16*)pWd, ds, out, H_DIM, I_DIM);
}

// round 9
// speedup vs baseline: 1.3035x; 1.3035x over previous
#include <cuda_runtime.h>
#include <cuda_bf16.h>
#include <cuda_fp8.h>
#include <math.h>
#include <stdint.h>

// Problem shape: x[M,H], gate/up [I,H], down [H,I]
#define M_DIM 4096
#define H_DIM 4096
#define I_DIM 14336
#define KB_H (H_DIM / 128)   // 32
#define KB_I (I_DIM / 128)   // 112

// ---------------- scratch (device globals; no allocation) ----------------
__device__ uint8_t g_Aq[(size_t)M_DIM * H_DIM];     // e4m3 codes of quantized x
__device__ float   g_As[(size_t)M_DIM * KB_H];
__device__ uint8_t g_Wg[(size_t)I_DIM * H_DIM];     // e4m3 weight codes
__device__ uint8_t g_Wu[(size_t)I_DIM * H_DIM];
__device__ uint8_t g_Wd[(size_t)H_DIM * I_DIM];
__device__ float   g_gate[(size_t)M_DIM * I_DIM];
__device__ float   g_up[(size_t)M_DIM * I_DIM];
__device__ uint8_t g_Hq[(size_t)M_DIM * I_DIM];
__device__ float   g_Hs[(size_t)M_DIM * KB_I];
__device__ int     g_wfmt;   // 0 = raw e4m3 bytes, 1 = float32, 2 = bfloat16

// ---------------- weight dtype detection (device-side, deterministic) ----------------
__global__ void detect_kernel(const void* __restrict__ w) {
    __shared__ int c32, c16;
    int t = threadIdx.x;
    if (t == 0) { c32 = 0; c16 = 0; }
    __syncthreads();
    const float* f = (const float*)w;
    const __nv_bfloat16* b = (const __nv_bfloat16*)w;
    int l32 = 0, l16 = 0;
    for (int i = t; i < 16384; i += 256) {
        float v = f[i];
        if (fabsf(v) <= 448.0f) l32++;
        float u = __bfloat162float(b[i]);
        if (fabsf(u) <= 448.0f) l16++;
    }
    atomicAdd(&c32, l32);
    atomicAdd(&c16, l16);
    __syncthreads();
    if (t == 0) {
        int fmt = 0;
        if (c32 >= 16056) fmt = 1;
        else if (c16 >= 16056) fmt = 2;
        g_wfmt = fmt;
    }
}

// ---------------- weight convert -> raw e4m3 codes (vectorized x4) ----------------
__global__ void convert_w_kernel(const void* __restrict__ src,
                                 uint8_t* __restrict__ dst, size_t n4) {
    int fmt = g_wfmt;
    size_t i = (size_t)blockIdx.x * blockDim.x + threadIdx.x;
    size_t stride = (size_t)gridDim.x * blockDim.x;
    uchar4* d4 = (uchar4*)dst;
    if (fmt == 1) {
        const float4* s = (const float4*)src;
        for (; i < n4; i += stride) {
            float4 v = s[i];
            uchar4 o;
            o.x = __nv_fp8_e4m3(v.x).__x;
            o.y = __nv_fp8_e4m3(v.y).__x;
            o.z = __nv_fp8_e4m3(v.z).__x;
            o.w = __nv_fp8_e4m3(v.w).__x;
            d4[i] = o;
        }
    } else if (fmt == 2) {
        const __nv_bfloat162* s = (const __nv_bfloat162*)src;
        for (; i < n4; i += stride) {
            __nv_bfloat162 a = s[i * 2], b = s[i * 2 + 1];
            uchar4 o;
            o.x = __nv_fp8_e4m3(__bfloat162float(a.x)).__x;
            o.y = __nv_fp8_e4m3(__bfloat162float(a.y)).__x;
            o.z = __nv_fp8_e4m3(__bfloat162float(b.x)).__x;
            o.w = __nv_fp8_e4m3(__bfloat162float(b.y)).__x;
            d4[i] = o;
        }
    } else {
        const uchar4* s = (const uchar4*)src;
        for (; i < n4; i += stride) d4[i] = s[i];
    }
}

// ---------------- per-token per-128-group fake-quant of activations ----------------
__global__ void quant_act_kernel(const float* __restrict__ X,
                                 uint8_t* __restrict__ Q,
                                 float* __restrict__ S, int Kdim) {
    const int KB = Kdim >> 7;
    const int g = blockIdx.x;
    const int m = blockIdx.y;
    const int t = threadIdx.x;
    size_t base = (size_t)m * Kdim + (size_t)g * 128;
    float v = X[base + t];
    float a = fabsf(v);
#pragma unroll
    for (int o = 16; o > 0; o >>= 1) a = fmaxf(a, __shfl_xor_sync(0xffffffffu, a, o));
    __shared__ float red[4];
    if ((t & 31) == 0) red[t >> 5] = a;
    __syncthreads();
    float amax = fmaxf(fmaxf(red[0], red[1]), fmaxf(red[2], red[3]));
    float s = fmaxf(amax * (1.0f / 448.0f), 1e-12f);
    float qv = fminf(fmaxf(v / s, -448.0f), 448.0f);
    Q[base + t] = __nv_fp8_e4m3(qv).__x;
    if (t == 0) S[(size_t)m * KB + g] = s;
}

// ---------------- silu(gate)*up + fake-quant ----------------
__global__ void silu_quant_kernel(const float* __restrict__ G,
                                  const float* __restrict__ U,
                                  uint8_t* __restrict__ Q,
                                  float* __restrict__ S, int Kdim) {
    const int KB = Kdim >> 7;
    const int g = blockIdx.x;
    const int m = blockIdx.y;
    const int t = threadIdx.x;
    size_t base = (size_t)m * Kdim + (size_t)g * 128;
    float gv = G[base + t];
    float uv = U[base + t];
    float v = (gv / (1.0f + expf(-gv))) * uv;
    float a = fabsf(v);
#pragma unroll
    for (int o = 16; o > 0; o >>= 1) a = fmaxf(a, __shfl_xor_sync(0xffffffffu, a, o));
    __shared__ float red[4];
    if ((t & 31) == 0) red[t >> 5] = a;
    __syncthreads();
    float amax = fmaxf(fmaxf(red[0], red[1]), fmaxf(red[2], red[3]));
    float s = fmaxf(amax * (1.0f / 448.0f), 1e-12f);
    float qv = fminf(fmaxf(v / s, -448.0f), 448.0f);
    Q[base + t] = __nv_fp8_e4m3(qv).__x;
    if (t == 0) S[(size_t)m * KB + g] = s;
}

// =================== FP8 mma.sync block-scaled GEMM ===================
// C[m,n] = sum_kb As[m,kb]*Ws[nb,kb]*(sum_{k in kb} a[m,k]*b[n,k])
// Tile 128x128, BK = 128 bytes (one full quant block per smem stage),
// 4-stage cp.async ring, fp8 m16n8k32 mma, fp32 promotion per 128-K block.

#define GEMM_THREADS 256
#define ROW_BYTES 144                 // 128 + 16 pad: conflict-free ldmatrix
#define STAGE_A (128 * ROW_BYTES)     // 18432
#define STAGE_BYTES (2 * STAGE_A)     // 36864 (A tile + B tile)
#define NSTAGE 4
#define GEMM_SMEM (NSTAGE * STAGE_BYTES)

__device__ __forceinline__ uint32_t smem_to_u32(const void* p) {
    uint32_t a;
    asm("{ .reg .u64 t; cvta.to.shared.u64 t, %1; cvt.u32.u64 %0, t; }" : "=r"(a) : "l"(p));
    return a;
}
__device__ __forceinline__ void mma_fp8(float* c, const uint32_t* a, const uint32_t* b) {
    asm volatile(
        "mma.sync.aligned.m16n8k32.row.col.f32.e4m3.e4m3.f32 "
        "{%0,%1,%2,%3},{%4,%5,%6,%7},{%8,%9},{%0,%1,%2,%3};\n"
        : "+f"(c[0]), "+f"(c[1]), "+f"(c[2]), "+f"(c[3])
        : "r"(a[0]), "r"(a[1]), "r"(a[2]), "r"(a[3]), "r"(b[0]), "r"(b[1]));
}
__device__ __forceinline__ void ldsm4(uint32_t* r, uint32_t addr) {
    asm volatile("ldmatrix.sync.aligned.m8n8.x4.shared.b16 {%0,%1,%2,%3},[%4];\n"
                 : "=r"(r[0]), "=r"(r[1]), "=r"(r[2]), "=r"(r[3]) : "r"(addr));
}
__device__ __forceinline__ void ldsm2(uint32_t* r, uint32_t addr) {
    asm volatile("ldmatrix.sync.aligned.m8n8.x2.shared.b16 {%0,%1},[%2];\n"
                 : "=r"(r[0]), "=r"(r[1]) : "r"(addr));
}

// Load one 128x128-byte A tile + B tile into a pipeline stage (16B cp.async).
__device__ __forceinline__ void load_stage(
    const uint8_t* __restrict__ A, const uint8_t* __restrict__ B,
    int Kdim, int m0, int n0, int kb, uint32_t stage_smem, int tid) {
    const uint8_t* Ag = A + (size_t)m0 * Kdim + (size_t)kb * 128;
    const uint8_t* Bg = B + (size_t)n0 * Kdim + (size_t)kb * 128;
#pragma unroll
    for (int it = 0; it < 8; it++) {
        int i = it * GEMM_THREADS + tid;          // 0..2047 16B chunks
        int half = i >> 10;                       // 0 = A, 1 = B
        int c = i & 1023;
        int r = c >> 3;
        int col = (c & 7) * 16;
        const uint8_t* g = half ? (Bg + (size_t)r * Kdim + col)
                                : (Ag + (size_t)r * Kdim + col);
        uint32_t d = stage_smem + (uint32_t)half * STAGE_A + (uint32_t)(r * ROW_BYTES + col);
        asm volatile("cp.async.cg.shared.global [%0], [%1], 16;\n" :: "r"(d), "l"(g));
    }
    asm volatile("cp.async.commit_group;\n" ::: "memory");
}

__global__ void __launch_bounds__(GEMM_THREADS, 1)
gemm_fp8(const uint8_t* __restrict__ A, const float* __restrict__ As,
         const uint8_t* __restrict__ B, const float* __restrict__ Bs,
         float* __restrict__ C, int Ndim, int Kdim) {
    extern __shared__ char smem_raw[];
    const uint32_t sbase = smem_to_u32(smem_raw);

    const int KB = Kdim >> 7;
    const int tid = threadIdx.x;
    const int lane = tid & 31;
    const int w = tid >> 5;
    const int wm = (w & 3) * 32;   // warp m offset
    const int wn = (w >> 2) * 64;  // warp n offset
    const int m0 = blockIdx.y * 128;
    const int n0 = blockIdx.x * 128;
    const int nb = blockIdx.x;

    // ldmatrix per-lane addressing (u16 view of fp8 bytes)
    const int a_r = (((lane >> 3) & 1) << 3) + (lane & 7);  // row within 16
    const int a_kb = (lane >> 4) << 4;                      // byte: 0 or 16
    const int b_r = lane & 7;
    const int b_kb = ((lane >> 3) & 1) << 4;                // byte: 0 or 16

    // per-thread smem byte offsets (excluding ks term)
    const uint32_t aoff = (uint32_t)((wm + a_r) * ROW_BYTES + a_kb);
    const uint32_t boff = (uint32_t)(STAGE_A + (wn + b_r) * ROW_BYTES + b_kb);

    float fc[2][8][4], pc[2][8][4];
#pragma unroll
    for (int i = 0; i < 2; i++)
#pragma unroll
        for (int j = 0; j < 8; j++)
#pragma unroll
            for (int k = 0; k < 4; k++) { fc[i][j][k] = 0.0f; pc[i][j][k] = 0.0f; }

    // promotion scale rows
    const int pr0 = m0 + wm + (lane >> 2);
    const float* BsRow = Bs + (size_t)nb * KB;

    // prologue: stages 0..2
    load_stage(A, B, Kdim, m0, n0, 0, sbase + 0 * STAGE_BYTES, tid);
    load_stage(A, B, Kdim, m0, n0, 1, sbase + 1 * STAGE_BYTES, tid);
    load_stage(A, B, Kdim, m0, n0, 2, sbase + 2 * STAGE_BYTES, tid);

    for (int kb = 0; kb < KB; kb++) {
        asm volatile("cp.async.wait_group 2;\n" ::: "memory");
        __syncthreads();

        // prefetch stage kb+3 (overwrites stage consumed at kb-1; barrier above protects)
        if (kb + 3 < KB)
            load_stage(A, B, Kdim, m0, n0, kb + 3,
                       sbase + (uint32_t)((kb + 3) & 3) * STAGE_BYTES, tid);
        else
            asm volatile("cp.async.commit_group;\n" ::: "memory");

        const uint32_t sa = sbase + (uint32_t)(kb & 3) * STAGE_BYTES;
#pragma unroll
        for (int ks = 0; ks < 4; ks++) {
            uint32_t af[2][4], bf[8][2];
#pragma unroll
            for (int mt = 0; mt < 2; mt++)
                ldsm4(af[mt], sa + aoff + (uint32_t)(mt * 16 * ROW_BYTES) + (uint32_t)(ks * 32));
#pragma unroll
            for (int nt = 0; nt < 8; nt++)
                ldsm2(bf[nt], sa + boff + (uint32_t)(nt * 8 * ROW_BYTES) + (uint32_t)(ks * 32));
#pragma unroll
            for (int mt = 0; mt < 2; mt++)
#pragma unroll
                for (int nt = 0; nt < 8; nt++)
                    mma_fp8(pc[mt][nt], af[mt], bf[nt]);
        }

        // promote this 128-K block with fp32 scales
        float ws = BsRow[kb];
#pragma unroll
        for (int mt = 0; mt < 2; mt++) {
            int r0 = pr0 + mt * 16;
            float s0 = As[(size_t)r0 * KB + kb] * ws;
            float s1 = As[(size_t)(r0 + 8) * KB + kb] * ws;
#pragma unroll
            for (int nt = 0; nt < 8; nt++) {
                fc[mt][nt][0] += s0 * pc[mt][nt][0];
                fc[mt][nt][1] += s0 * pc[mt][nt][1];
                fc[mt][nt][2] += s1 * pc[mt][nt][2];
                fc[mt][nt][3] += s1 * pc[mt][nt][3];
                pc[mt][nt][0] = 0.0f; pc[mt][nt][1] = 0.0f;
                pc[mt][nt][2] = 0.0f; pc[mt][nt][3] = 0.0f;
            }
        }
    }

    // epilogue
#pragma unroll
    for (int mt = 0; mt < 2; mt++) {
        int r0 = pr0 + mt * 16;
#pragma unroll
        for (int nt = 0; nt < 8; nt++) {
            int c0 = n0 + wn + nt * 8 + (lane & 3) * 2;
            *(float2*)(C + (size_t)r0 * Ndim + c0) =
                make_float2(fc[mt][nt][0], fc[mt][nt][1]);
            *(float2*)(C + (size_t)(r0 + 8) * Ndim + c0) =
                make_float2(fc[mt][nt][2], fc[mt][nt][3]);
        }
    }
}

// ---------------- launch ----------------
extern "C" void kernel_launch(void* const* d_in, const int* in_sizes, int n_in,
                              void* d_out, int out_size) {
    (void)in_sizes; (void)n_in; (void)out_size;
    const float* x  = (const float*)d_in[0];
    const void*  gw = d_in[1];
    const float* gs = (const float*)d_in[2];
    const void*  uw = d_in[3];
    const float* us = (const float*)d_in[4];
    const void*  dw = d_in[5];
    const float* ds = (const float*)d_in[6];
    float* out = (float*)d_out;

    static bool init = false;
    static void *pAq, *pAs, *pWg, *pWu, *pWd, *pG, *pU, *pHq, *pHs;
    if (!init) {
        cudaGetSymbolAddress(&pAq, g_Aq);
        cudaGetSymbolAddress(&pAs, g_As);
        cudaGetSymbolAddress(&pWg, g_Wg);
        cudaGetSymbolAddress(&pWu, g_Wu);
        cudaGetSymbolAddress(&pWd, g_Wd);
        cudaGetSymbolAddress(&pG,  g_gate);
        cudaGetSymbolAddress(&pU,  g_up);
        cudaGetSymbolAddress(&pHq, g_Hq);
        cudaGetSymbolAddress(&pHs, g_Hs);
        cudaFuncSetAttribute(gemm_fp8, cudaFuncAttributeMaxDynamicSharedMemorySize, GEMM_SMEM);
        init = true;
    }

    detect_kernel<<<1, 256>>>(gw);
    convert_w_kernel<<<2048, 256>>>(gw, (uint8_t*)pWg, (size_t)I_DIM * H_DIM / 4);
    convert_w_kernel<<<2048, 256>>>(uw, (uint8_t*)pWu, (size_t)I_DIM * H_DIM / 4);
    convert_w_kernel<<<2048, 256>>>(dw, (uint8_t*)pWd, (size_t)H_DIM * I_DIM / 4);

    quant_act_kernel<<<dim3(KB_H, M_DIM), 128>>>(x, (uint8_t*)pAq, (float*)pAs, H_DIM);

    dim3 grid1(I_DIM / 128, M_DIM / 128);
    gemm_fp8<<<grid1, GEMM_THREADS, GEMM_SMEM>>>((uint8_t*)pAq, (float*)pAs,
                                                 (uint8_t*)pWg, gs, (float*)pG, I_DIM, H_DIM);
    gemm_fp8<<<grid1, GEMM_THREADS, GEMM_SMEM>>>((uint8_t*)pAq, (float*)pAs,
                                                 (uint8_t*)pWu, us, (float*)pU, I_DIM, H_DIM);

    silu_quant_kernel<<<dim3(KB_I, M_DIM), 128>>>((float*)pG, (float*)pU,
                                                  (uint8_t*)pHq, (float*)pHs, I_DIM);

    dim3 grid2(H_DIM / 128, M_DIM / 128);
    gemm_fp8<<<grid2, GEMM_THREADS, GEMM_SMEM>>>((uint8_t*)pHq, (float*)pHs,
                                                 (uint8_t*)pWd, ds, out, H_DIM, I_DIM);
}

// round 10
// speedup vs baseline: 1.3208x; 1.0133x over previous
#include <cuda_runtime.h>
#include <cuda_bf16.h>
#include <cuda_fp8.h>
#include <math.h>
#include <stdint.h>

// Problem shape: x[M,H], gate/up [I,H], down [H,I]
#define M_DIM 4096
#define H_DIM 4096
#define I_DIM 14336
#define KB_H (H_DIM / 128)   // 32
#define KB_I (I_DIM / 128)   // 112

// ---------------- scratch (device globals; no allocation) ----------------
__device__ uint8_t g_Aq[(size_t)M_DIM * H_DIM];     // e4m3 codes of quantized x
__device__ float   g_As[(size_t)M_DIM * KB_H];
__device__ uint8_t g_Wg[(size_t)I_DIM * H_DIM];     // e4m3 weight codes
__device__ uint8_t g_Wu[(size_t)I_DIM * H_DIM];
__device__ uint8_t g_Wd[(size_t)H_DIM * I_DIM];
__device__ float   g_gate[(size_t)M_DIM * I_DIM];
__device__ float   g_up[(size_t)M_DIM * I_DIM];
__device__ uint8_t g_Hq[(size_t)M_DIM * I_DIM];
__device__ float   g_Hs[(size_t)M_DIM * KB_I];
__device__ int     g_wfmt;   // 0 = raw e4m3 bytes, 1 = float32, 2 = bfloat16

// ---------------- weight dtype detection (device-side, deterministic) ----------------
__global__ void detect_kernel(const void* __restrict__ w) {
    __shared__ int c32, c16;
    int t = threadIdx.x;
    if (t == 0) { c32 = 0; c16 = 0; }
    __syncthreads();
    const float* f = (const float*)w;
    const __nv_bfloat16* b = (const __nv_bfloat16*)w;
    int l32 = 0, l16 = 0;
    for (int i = t; i < 16384; i += 256) {
        float v = f[i];
        if (fabsf(v) <= 448.0f) l32++;
        float u = __bfloat162float(b[i]);
        if (fabsf(u) <= 448.0f) l16++;
    }
    atomicAdd(&c32, l32);
    atomicAdd(&c16, l16);
    __syncthreads();
    if (t == 0) {
        int fmt = 0;
        if (c32 >= 16056) fmt = 1;
        else if (c16 >= 16056) fmt = 2;
        g_wfmt = fmt;
    }
}

// ---------------- weight convert -> raw e4m3 codes (vectorized x4) ----------------
__global__ void convert_w_kernel(const void* __restrict__ src,
                                 uint8_t* __restrict__ dst, size_t n4) {
    int fmt = g_wfmt;
    size_t i = (size_t)blockIdx.x * blockDim.x + threadIdx.x;
    size_t stride = (size_t)gridDim.x * blockDim.x;
    uchar4* d4 = (uchar4*)dst;
    if (fmt == 1) {
        const float4* s = (const float4*)src;
        for (; i < n4; i += stride) {
            float4 v = s[i];
            uchar4 o;
            o.x = __nv_fp8_e4m3(v.x).__x;
            o.y = __nv_fp8_e4m3(v.y).__x;
            o.z = __nv_fp8_e4m3(v.z).__x;
            o.w = __nv_fp8_e4m3(v.w).__x;
            d4[i] = o;
        }
    } else if (fmt == 2) {
        const __nv_bfloat162* s = (const __nv_bfloat162*)src;
        for (; i < n4; i += stride) {
            __nv_bfloat162 a = s[i * 2], b = s[i * 2 + 1];
            uchar4 o;
            o.x = __nv_fp8_e4m3(__bfloat162float(a.x)).__x;
            o.y = __nv_fp8_e4m3(__bfloat162float(a.y)).__x;
            o.z = __nv_fp8_e4m3(__bfloat162float(b.x)).__x;
            o.w = __nv_fp8_e4m3(__bfloat162float(b.y)).__x;
            d4[i] = o;
        }
    } else {
        const uchar4* s = (const uchar4*)src;
        for (; i < n4; i += stride) d4[i] = s[i];
    }
}

// ---------------- per-token per-128-group fake-quant of activations ----------------
__global__ void quant_act_kernel(const float* __restrict__ X,
                                 uint8_t* __restrict__ Q,
                                 float* __restrict__ S, int Kdim) {
    const int KB = Kdim >> 7;
    const int g = blockIdx.x;
    const int m = blockIdx.y;
    const int t = threadIdx.x;
    size_t base = (size_t)m * Kdim + (size_t)g * 128;
    float v = X[base + t];
    float a = fabsf(v);
#pragma unroll
    for (int o = 16; o > 0; o >>= 1) a = fmaxf(a, __shfl_xor_sync(0xffffffffu, a, o));
    __shared__ float red[4];
    if ((t & 31) == 0) red[t >> 5] = a;
    __syncthreads();
    float amax = fmaxf(fmaxf(red[0], red[1]), fmaxf(red[2], red[3]));
    float s = fmaxf(amax * (1.0f / 448.0f), 1e-12f);
    float qv = fminf(fmaxf(v / s, -448.0f), 448.0f);
    Q[base + t] = __nv_fp8_e4m3(qv).__x;
    if (t == 0) S[(size_t)m * KB + g] = s;
}

// ---------------- silu(gate)*up + fake-quant ----------------
__global__ void silu_quant_kernel(const float* __restrict__ G,
                                  const float* __restrict__ U,
                                  uint8_t* __restrict__ Q,
                                  float* __restrict__ S, int Kdim) {
    const int KB = Kdim >> 7;
    const int g = blockIdx.x;
    const int m = blockIdx.y;
    const int t = threadIdx.x;
    size_t base = (size_t)m * Kdim + (size_t)g * 128;
    float gv = G[base + t];
    float uv = U[base + t];
    float v = (gv / (1.0f + expf(-gv))) * uv;
    float a = fabsf(v);
#pragma unroll
    for (int o = 16; o > 0; o >>= 1) a = fmaxf(a, __shfl_xor_sync(0xffffffffu, a, o));
    __shared__ float red[4];
    if ((t & 31) == 0) red[t >> 5] = a;
    __syncthreads();
    float amax = fmaxf(fmaxf(red[0], red[1]), fmaxf(red[2], red[3]));
    float s = fmaxf(amax * (1.0f / 448.0f), 1e-12f);
    float qv = fminf(fmaxf(v / s, -448.0f), 448.0f);
    Q[base + t] = __nv_fp8_e4m3(qv).__x;
    if (t == 0) S[(size_t)m * KB + g] = s;
}

// =================== FP8 mma.sync block-scaled GEMM ===================
// C[m,n] = sum_kb As[m,kb]*Ws[nb,kb]*(sum_{k in kb} a[m,k]*b[n,k])
// Tile 128x128, 512 threads (16 warps, 4/SMSP), warp tile 16x64.
// 5-stage cp.async ring (BK=128 bytes = one quant block per stage),
// fp8 m16n8k32 mma, fp32 promotion per 128-K block, prefetched scales.

#define GEMM_THREADS 512
#define ROW_BYTES 144                 // 128 + 16 pad: conflict-free ldmatrix
#define STAGE_A (128 * ROW_BYTES)     // 18432
#define STAGE_BYTES (2 * STAGE_A)     // 36864 (A tile + B tile)
#define NSTAGE 5
#define GEMM_SMEM (NSTAGE * STAGE_BYTES)   // 184320

__device__ __forceinline__ uint32_t smem_to_u32(const void* p) {
    uint32_t a;
    asm("{ .reg .u64 t; cvta.to.shared.u64 t, %1; cvt.u32.u64 %0, t; }" : "=r"(a) : "l"(p));
    return a;
}
__device__ __forceinline__ void mma_fp8(float* c, const uint32_t* a, const uint32_t* b) {
    asm volatile(
        "mma.sync.aligned.m16n8k32.row.col.f32.e4m3.e4m3.f32 "
        "{%0,%1,%2,%3},{%4,%5,%6,%7},{%8,%9},{%0,%1,%2,%3};\n"
        : "+f"(c[0]), "+f"(c[1]), "+f"(c[2]), "+f"(c[3])
        : "r"(a[0]), "r"(a[1]), "r"(a[2]), "r"(a[3]), "r"(b[0]), "r"(b[1]));
}
__device__ __forceinline__ void ldsm4(uint32_t* r, uint32_t addr) {
    asm volatile("ldmatrix.sync.aligned.m8n8.x4.shared.b16 {%0,%1,%2,%3},[%4];\n"
                 : "=r"(r[0]), "=r"(r[1]), "=r"(r[2]), "=r"(r[3]) : "r"(addr));
}

// Load one 128x128-byte A tile + B tile into a pipeline stage (16B cp.async).
__device__ __forceinline__ void load_stage(
    const uint8_t* __restrict__ A, const uint8_t* __restrict__ B,
    int Kdim, int m0, int n0, int kb, uint32_t stage_smem, int tid) {
    const uint8_t* Ag = A + (size_t)m0 * Kdim + (size_t)kb * 128;
    const uint8_t* Bg = B + (size_t)n0 * Kdim + (size_t)kb * 128;
#pragma unroll
    for (int it = 0; it < 4; it++) {
        int i = it * GEMM_THREADS + tid;          // 0..2047 16B chunks
        int half = i >> 10;                       // 0 = A, 1 = B
        int c = i & 1023;
        int r = c >> 3;
        int col = (c & 7) * 16;
        const uint8_t* g = half ? (Bg + (size_t)r * Kdim + col)
                                : (Ag + (size_t)r * Kdim + col);
        uint32_t d = stage_smem + (uint32_t)half * STAGE_A + (uint32_t)(r * ROW_BYTES + col);
        asm volatile("cp.async.cg.shared.global [%0], [%1], 16;\n" :: "r"(d), "l"(g));
    }
    asm volatile("cp.async.commit_group;\n" ::: "memory");
}

__global__ void __launch_bounds__(GEMM_THREADS, 1)
gemm_fp8(const uint8_t* __restrict__ A, const float* __restrict__ As,
         const uint8_t* __restrict__ B, const float* __restrict__ Bs,
         float* __restrict__ C, int Ndim, int Kdim) {
    extern __shared__ char smem_raw[];
    const uint32_t sbase = smem_to_u32(smem_raw);

    const int KB = Kdim >> 7;
    const int tid = threadIdx.x;
    const int lane = tid & 31;
    const int w = tid >> 5;
    const int wm = (w & 7) * 16;    // warp m offset (8 m-tiles of 16 rows)
    const int wn = (w >> 3) * 64;   // warp n offset (2 n-halves of 64 cols)
    const int m0 = blockIdx.y * 128;
    const int n0 = blockIdx.x * 128;
    const int nb = blockIdx.x;

    // A ldmatrix addressing (u16 view of fp8 bytes): 16 rows x 32 bytes per ks
    const int a_r = (((lane >> 3) & 1) << 3) + (lane & 7);  // row within 16
    const int a_kb = (lane >> 4) << 4;                      // byte 0 or 16
    const uint32_t aoff = (uint32_t)((wm + a_r) * ROW_BYTES + a_kb);

    // B paired ldmatrix addressing: pair p covers n-tiles 2p, 2p+1 (16 rows)
    const int g4 = lane >> 3;                               // lane group 0..3
    const int b_row = ((g4 >> 1) << 3) + (lane & 7);        // row within 16
    const int b_kb = (g4 & 1) << 4;                         // byte 0 or 16
    const uint32_t boff = (uint32_t)(STAGE_A + (wn + b_row) * ROW_BYTES + b_kb);

    float fc[8][4], pc[8][4];
#pragma unroll
    for (int j = 0; j < 8; j++)
#pragma unroll
        for (int k = 0; k < 4; k++) { fc[j][k] = 0.0f; pc[j][k] = 0.0f; }

    // promotion scale rows (this thread owns rows pr0 and pr0+8)
    const int pr0 = m0 + wm + (lane >> 2);
    const float* AsR0 = As + (size_t)pr0 * KB;
    const float* AsR1 = As + (size_t)(pr0 + 8) * KB;
    const float* BsRow = Bs + (size_t)nb * KB;

    // prologue: stages 0..3
    load_stage(A, B, Kdim, m0, n0, 0, sbase + 0 * STAGE_BYTES, tid);
    load_stage(A, B, Kdim, m0, n0, 1, sbase + 1 * STAGE_BYTES, tid);
    load_stage(A, B, Kdim, m0, n0, 2, sbase + 2 * STAGE_BYTES, tid);
    load_stage(A, B, Kdim, m0, n0, 3, sbase + 3 * STAGE_BYTES, tid);

    // scales for kb=0 prefetched before the loop
    float sA0 = AsR0[0], sA1 = AsR1[0], sW = BsRow[0];

    for (int kb = 0; kb < KB; kb++) {
        asm volatile("cp.async.wait_group 3;\n" ::: "memory");
        __syncthreads();

        // prefetch stage kb+4
        if (kb + 4 < KB)
            load_stage(A, B, Kdim, m0, n0, kb + 4,
                       sbase + (uint32_t)((kb + 4) % NSTAGE) * STAGE_BYTES, tid);
        else
            asm volatile("cp.async.commit_group;\n" ::: "memory");

        // prefetch next block's scales (consumed next iteration)
        float nA0 = 0.0f, nA1 = 0.0f, nW = 0.0f;
        if (kb + 1 < KB) { nA0 = AsR0[kb + 1]; nA1 = AsR1[kb + 1]; nW = BsRow[kb + 1]; }

        const uint32_t sa = sbase + (uint32_t)(kb % NSTAGE) * STAGE_BYTES;
#pragma unroll
        for (int ks = 0; ks < 4; ks++) {
            uint32_t af[4], bf[8][2];
            ldsm4(af, sa + aoff + (uint32_t)(ks * 32));
#pragma unroll
            for (int p = 0; p < 2; p++) {
                uint32_t q[4];
                ldsm4(q, sa + boff + (uint32_t)(p * 32 * ROW_BYTES) + (uint32_t)(ks * 32));
                bf[4 * p + 0][0] = q[0]; bf[4 * p + 0][1] = q[1];
                bf[4 * p + 1][0] = q[2]; bf[4 * p + 1][1] = q[3];
                // second pair of n-tiles for this p half
                uint32_t q2[4];
                ldsm4(q2, sa + boff + (uint32_t)((p * 32 + 16) * ROW_BYTES) + (uint32_t)(ks * 32));
                bf[4 * p + 2][0] = q2[0]; bf[4 * p + 2][1] = q2[1];
                bf[4 * p + 3][0] = q2[2]; bf[4 * p + 3][1] = q2[3];
            }
#pragma unroll
            for (int nt = 0; nt < 8; nt++)
                mma_fp8(pc[nt], af, bf[nt]);
        }

        // promote this 128-K block with fp32 scales
        float s0 = sA0 * sW;
        float s1 = sA1 * sW;
#pragma unroll
        for (int nt = 0; nt < 8; nt++) {
            fc[nt][0] += s0 * pc[nt][0];
            fc[nt][1] += s0 * pc[nt][1];
            fc[nt][2] += s1 * pc[nt][2];
            fc[nt][3] += s1 * pc[nt][3];
            pc[nt][0] = 0.0f; pc[nt][1] = 0.0f;
            pc[nt][2] = 0.0f; pc[nt][3] = 0.0f;
        }
        sA0 = nA0; sA1 = nA1; sW = nW;
    }

    // epilogue: rows pr0 and pr0+8, cols n0+wn + nt*8 + (lane&3)*2
#pragma unroll
    for (int nt = 0; nt < 8; nt++) {
        int c0 = n0 + wn + nt * 8 + (lane & 3) * 2;
        *(float2*)(C + (size_t)pr0 * Ndim + c0) = make_float2(fc[nt][0], fc[nt][1]);
        *(float2*)(C + (size_t)(pr0 + 8) * Ndim + c0) = make_float2(fc[nt][2], fc[nt][3]);
    }
}

// ---------------- launch ----------------
extern "C" void kernel_launch(void* const* d_in, const int* in_sizes, int n_in,
                              void* d_out, int out_size) {
    (void)in_sizes; (void)n_in; (void)out_size;
    const float* x  = (const float*)d_in[0];
    const void*  gw = d_in[1];
    const float* gs = (const float*)d_in[2];
    const void*  uw = d_in[3];
    const float* us = (const float*)d_in[4];
    const void*  dw = d_in[5];
    const float* ds = (const float*)d_in[6];
    float* out = (float*)d_out;

    static bool init = false;
    static void *pAq, *pAs, *pWg, *pWu, *pWd, *pG, *pU, *pHq, *pHs;
    if (!init) {
        cudaGetSymbolAddress(&pAq, g_Aq);
        cudaGetSymbolAddress(&pAs, g_As);
        cudaGetSymbolAddress(&pWg, g_Wg);
        cudaGetSymbolAddress(&pWu, g_Wu);
        cudaGetSymbolAddress(&pWd, g_Wd);
        cudaGetSymbolAddress(&pG,  g_gate);
        cudaGetSymbolAddress(&pU,  g_up);
        cudaGetSymbolAddress(&pHq, g_Hq);
        cudaGetSymbolAddress(&pHs, g_Hs);
        cudaFuncSetAttribute(gemm_fp8, cudaFuncAttributeMaxDynamicSharedMemorySize, GEMM_SMEM);
        init = true;
    }

    detect_kernel<<<1, 256>>>(gw);
    convert_w_kernel<<<2048, 256>>>(gw, (uint8_t*)pWg, (size_t)I_DIM * H_DIM / 4);
    convert_w_kernel<<<2048, 256>>>(uw, (uint8_t*)pWu, (size_t)I_DIM * H_DIM / 4);
    convert_w_kernel<<<2048, 256>>>(dw, (uint8_t*)pWd, (size_t)H_DIM * I_DIM / 4);

    quant_act_kernel<<<dim3(KB_H, M_DIM), 128>>>(x, (uint8_t*)pAq, (float*)pAs, H_DIM);

    dim3 grid1(I_DIM / 128, M_DIM / 128);
    gemm_fp8<<<grid1, GEMM_THREADS, GEMM_SMEM>>>((uint8_t*)pAq, (float*)pAs,
                                                 (uint8_t*)pWg, gs, (float*)pG, I_DIM, H_DIM);
    gemm_fp8<<<grid1, GEMM_THREADS, GEMM_SMEM>>>((uint8_t*)pAq, (float*)pAs,
                                                 (uint8_t*)pWu, us, (float*)pU, I_DIM, H_DIM);

    silu_quant_kernel<<<dim3(KB_I, M_DIM), 128>>>((float*)pG, (float*)pU,
                                                  (uint8_t*)pHq, (float*)pHs, I_DIM);

    dim3 grid2(H_DIM / 128, M_DIM / 128);
    gemm_fp8<<<grid2, GEMM_THREADS, GEMM_SMEM>>>((uint8_t*)pHq, (float*)pHs,
                                                 (uint8_t*)pWd, ds, out, H_DIM, I_DIM);
}